// round 4
// baseline (speedup 1.0000x reference)
#include <cuda_runtime.h>
#include <math.h>

#define NN   4096
#define DD   128
#define HH   128
#define EQN  16384
#define MAXE 131072
#define MAXNNZ 262144

// ---------------- device scratch ----------------
static __device__ float  g_aval[MAXE];
static __device__ float  g_d[NN];
static __device__ float  g_invd[NN];
static __device__ float  g_pi[NN];
static __device__ int    g_deg[NN];
static __device__ int    g_rowstart[NN + 1];
static __device__ int    g_rowpos[NN];
static __device__ int    g_cols[MAXNNZ];
static __device__ float  g_cvals[MAXNNZ];
static __device__ int    g_qcnt[NN];
static __device__ int    g_qstart[NN + 1];
static __device__ int    g_qpos[NN];
static __device__ int    g_qid[EQN];
static __device__ float  g_pval[EQN];
static __device__ double g_G1, g_G2, g_sumpi;
static __device__ float  g_sumd;
static __device__ float  g_XW[NN * HH];
static __device__ int    g_is64;

__device__ __forceinline__ int idx_at(const int* __restrict__ p, int k) {
    return g_is64 ? p[2 * k] : p[k];
}

// ---- packed fp32 (Blackwell f32x2) ----
__device__ __forceinline__ unsigned long long pk2(float lo, float hi) {
    unsigned long long r;
    asm("mov.b64 %0, {%1, %2};" : "=l"(r) : "f"(lo), "f"(hi));
    return r;
}
__device__ __forceinline__ void upk2(unsigned long long v, float& lo, float& hi) {
    asm("mov.b64 {%0, %1}, %2;" : "=f"(lo), "=f"(hi) : "l"(v));
}
__device__ __forceinline__ void ffma2(unsigned long long& acc,
                                      unsigned long long a, unsigned long long b) {
    asm("fma.rn.f32x2 %0, %1, %2, %0;" : "+l"(acc) : "l"(a), "l"(b));
}

// ---------------- kernels ----------------

// init + int-width detect
__global__ void k_init(const int* __restrict__ AE) {
    int i = blockIdx.x * blockDim.x + threadIdx.x;
    if (i < NN) { g_d[i] = 1.0f; g_deg[i] = 1; g_qcnt[i] = 0; }
    if (i == 0) { g_G1 = 0.0; g_G2 = 0.0; g_sumpi = 0.0; }
    if (blockIdx.x == 0) {
        __shared__ int any;
        if (threadIdx.x == 0) any = 0;
        __syncthreads();
        int loc = 0;
        for (int q = threadIdx.x; q < 1024; q += blockDim.x)
            if (AE[2 * q + 1] != 0) loc = 1;
        if (loc) atomicOr(&any, 1);
        __syncthreads();
        if (threadIdx.x == 0) g_is64 = (any == 0) ? 1 : 0;
    }
}

// XW = X @ W1[0:128,:]  (blocks 0..127) fused with query row counts (blocks 128..255)
__global__ void __launch_bounds__(128) k_xw_qcnt(const float* __restrict__ X,
                                                 const float* __restrict__ W1,
                                                 const int* __restrict__ Q) {
    if ((int)blockIdx.x >= 128) {
        int q = (blockIdx.x - 128) * 128 + threadIdx.x;
        if (q < EQN) atomicAdd(&g_qcnt[idx_at(Q, 2 * q)], 1);
        return;
    }
    __shared__ float xs[32 * 132];
    int t = threadIdx.x;
    int r0 = blockIdx.x * 32;
    int le = t >> 2, c = t & 3;
    const float* xr = X + (size_t)(r0 + le) * DD;
#pragma unroll
    for (int i = 0; i < 32; i++) { int k = c * 32 + i; xs[le * 132 + k] = xr[k]; }
    __syncthreads();
    float acc[32];
#pragma unroll
    for (int e = 0; e < 32; e++) acc[e] = 0.0f;
    for (int k = 0; k < 128; k++) {
        float w = W1[k * 128 + t];
#pragma unroll
        for (int e = 0; e < 32; e++) acc[e] = fmaf(w, xs[e * 132 + k], acc[e]);
    }
#pragma unroll
    for (int e = 0; e < 32; e++) g_XW[(size_t)(r0 + e) * 128 + t] = acc[e];
}

// Edge MLP (f32x2) fused with per-edge A_enh accumulation.
// 128 threads, 32 edges/block; thread t owns output column t; acc packs edge pairs.
#define FS 36
__global__ void __launch_bounds__(128) k_mlp(const float* __restrict__ X,
                                             const int* __restrict__ AE,
                                             const float* __restrict__ A,
                                             const float* __restrict__ S,
                                             const float* __restrict__ W1,
                                             const float* __restrict__ b1,
                                             const float* __restrict__ W2,
                                             const float* __restrict__ b2,
                                             const float* __restrict__ W3,
                                             const float* __restrict__ b3,
                                             int E) {
    __shared__ float buf[128 * FS];      // 18 KB: feat -> h1 -> h2 (transposed: buf[k*FS+edge])
    __shared__ int   su[32], sv[32];
    int t = threadIdx.x;                 // 0..127
    int e0 = blockIdx.x * 32;

    // ---- feature build: |x0-x1| transposed
    {
        int le = t >> 2, c = t & 3;
        int e = e0 + le;
        int u = 0, v = 0;
        if (e < E) { u = idx_at(AE, 2 * e); v = idx_at(AE, 2 * e + 1); }
        if (c == 0) { su[le] = u; sv[le] = v; }
        const float4* x04 = (const float4*)(X + (size_t)u * DD + c * 32);
        const float4* x14 = (const float4*)(X + (size_t)v * DD + c * 32);
        bool ok = (e < E);
#pragma unroll
        for (int i = 0; i < 8; i++) {
            float4 a = x04[i], b = x14[i];
            int k = c * 32 + 4 * i;
            buf[(k + 0) * FS + le] = ok ? fabsf(a.x - b.x) : 0.0f;
            buf[(k + 1) * FS + le] = ok ? fabsf(a.y - b.y) : 0.0f;
            buf[(k + 2) * FS + le] = ok ? fabsf(a.z - b.z) : 0.0f;
            buf[(k + 3) * FS + le] = ok ? fabsf(a.w - b.w) : 0.0f;
        }
    }
    __syncthreads();

    unsigned long long acc[16];          // edge pairs (2p, 2p+1), column t

    // ---- layer 1: acc = b1 + XW[u] + XW[v] + feat @ W1[128:256,:]
    {
        float bb = b1[t];
#pragma unroll
        for (int p = 0; p < 16; p++) {
            float lo = bb + g_XW[(size_t)su[2 * p] * 128 + t]
                          + g_XW[(size_t)sv[2 * p] * 128 + t];
            float hi = bb + g_XW[(size_t)su[2 * p + 1] * 128 + t]
                          + g_XW[(size_t)sv[2 * p + 1] * 128 + t];
            acc[p] = pk2(lo, hi);
        }
    }
#pragma unroll 4
    for (int k = 0; k < 128; k++) {
        float w = W1[(size_t)(128 + k) * 128 + t];
        unsigned long long wp = pk2(w, w);
        const double2* f4 = (const double2*)&buf[k * FS];
#pragma unroll
        for (int q = 0; q < 8; q++) {
            double2 d = f4[q];
            ffma2(acc[2 * q],     __double_as_longlong(d.x), wp);
            ffma2(acc[2 * q + 1], __double_as_longlong(d.y), wp);
        }
    }
    __syncthreads();   // all warps done reading features
    // relu -> h1, thread t writes row t (transposed)
#pragma unroll
    for (int p = 0; p < 8; p++) {
        float a0, a1, b0, b1v;
        upk2(acc[2 * p], a0, a1);
        upk2(acc[2 * p + 1], b0, b1v);
        *(float4*)&buf[t * FS + 4 * p] =
            make_float4(fmaxf(a0, 0.0f), fmaxf(a1, 0.0f), fmaxf(b0, 0.0f), fmaxf(b1v, 0.0f));
    }
    __syncthreads();

    // ---- layer 2
    {
        float bb = b2[t];
        unsigned long long bp = pk2(bb, bb);
#pragma unroll
        for (int p = 0; p < 16; p++) acc[p] = bp;
    }
#pragma unroll 4
    for (int k = 0; k < 128; k++) {
        float w = W2[(size_t)k * 128 + t];
        unsigned long long wp = pk2(w, w);
        const double2* f4 = (const double2*)&buf[k * FS];
#pragma unroll
        for (int q = 0; q < 8; q++) {
            double2 d = f4[q];
            ffma2(acc[2 * q],     __double_as_longlong(d.x), wp);
            ffma2(acc[2 * q + 1], __double_as_longlong(d.y), wp);
        }
    }
    __syncthreads();
    // relu -> h2
#pragma unroll
    for (int p = 0; p < 8; p++) {
        float a0, a1, b0, b1v;
        upk2(acc[2 * p], a0, a1);
        upk2(acc[2 * p + 1], b0, b1v);
        *(float4*)&buf[t * FS + 4 * p] =
            make_float4(fmaxf(a0, 0.0f), fmaxf(a1, 0.0f), fmaxf(b0, 0.0f), fmaxf(b1v, 0.0f));
    }
    __syncthreads();

    // ---- head + fused edge accumulation (one thread per edge)
    if (t < 32) {
        int eo = e0 + t;
        bool ok = (eo < E);
        int u = su[t], v = sv[t];
        size_t idx = ((size_t)u << 12) + (size_t)v;
        float av = A[idx];          // issued early to hide DRAM latency
        float sval = S[idx];
        float z = b3[1] - b3[0];
        for (int k = 0; k < 128; k++) {
            float wd = W3[2 * k + 1] - W3[2 * k + 0];
            z = fmaf(buf[k * FS + t], wd, z);
        }
        if (ok) {
            float val = 1.0f / (1.0f + __expf(-z));
            float a = 0.5f * av + 0.25f * val + 0.25f * sval;
            g_aval[eo] = a;
            atomicAdd(&g_d[u], a);
            atomicAdd(&g_d[v], a);
            atomicAdd(&g_deg[u], 1);
            atomicAdd(&g_deg[v], 1);
        }
    }
}

__global__ void __launch_bounds__(1024) k_scan() {
    __shared__ int sm[1024];
    __shared__ float sf[1024];
    int t = threadIdx.x;
    int v[4];

    int s = 0;
#pragma unroll
    for (int j = 0; j < 4; j++) { v[j] = g_deg[4 * t + j]; s += v[j]; }
    sm[t] = s;
    __syncthreads();
    for (int off = 1; off < 1024; off <<= 1) {
        int x = (t >= off) ? sm[t - off] : 0;
        __syncthreads();
        sm[t] += x;
        __syncthreads();
    }
    {
        int run = sm[t] - s;
#pragma unroll
        for (int j = 0; j < 4; j++) { g_rowstart[4 * t + j] = run; g_rowpos[4 * t + j] = run; run += v[j]; }
        if (t == 1023) g_rowstart[NN] = sm[1023];
    }
    __syncthreads();

    s = 0;
#pragma unroll
    for (int j = 0; j < 4; j++) { v[j] = g_qcnt[4 * t + j]; s += v[j]; }
    sm[t] = s;
    __syncthreads();
    for (int off = 1; off < 1024; off <<= 1) {
        int x = (t >= off) ? sm[t - off] : 0;
        __syncthreads();
        sm[t] += x;
        __syncthreads();
    }
    {
        int run = sm[t] - s;
#pragma unroll
        for (int j = 0; j < 4; j++) { g_qstart[4 * t + j] = run; g_qpos[4 * t + j] = run; run += v[j]; }
        if (t == 1023) g_qstart[NN] = sm[1023];
    }
    __syncthreads();

    float fs = 0.0f;
#pragma unroll
    for (int j = 0; j < 4; j++) fs += g_d[4 * t + j];
    sf[t] = fs;
    __syncthreads();
    for (int off = 512; off; off >>= 1) {
        if (t < off) sf[t] += sf[t + off];
        __syncthreads();
    }
    if (t == 0) g_sumd = sf[0];
}

__global__ void k_pi() {
    int i = blockIdx.x * blockDim.x + threadIdx.x;
    if (i >= NN) return;
    float di = g_d[i];
    float p = di / g_sumd;
    g_pi[i] = p;
    g_invd[i] = 1.0f / di;
    atomicAdd(&g_sumpi, (double)p);
    int idx = atomicAdd(&g_rowpos[i], 1);
    g_cols[idx] = i;
    g_cvals[idx] = 1.0f;
}

// fused: CSR scatter + query-id scatter
__global__ void k_scatter(const int* __restrict__ AE, const int* __restrict__ Q,
                          int E, int EB) {
    if ((int)blockIdx.x < EB) {
        int e = blockIdx.x * 256 + threadIdx.x;
        if (e >= E) return;
        int u = idx_at(AE, 2 * e), v = idx_at(AE, 2 * e + 1);
        float a = g_aval[e];
        int i1 = atomicAdd(&g_rowpos[u], 1); g_cols[i1] = v; g_cvals[i1] = a;
        int i2 = atomicAdd(&g_rowpos[v], 1); g_cols[i2] = u; g_cvals[i2] = a;
    } else {
        int q = (blockIdx.x - EB) * 256 + threadIdx.x;
        if (q >= EQN) return;
        int i = idx_at(Q, 2 * q);
        int idx = atomicAdd(&g_qpos[i], 1);
        g_qid[idx] = q;
    }
}

__global__ void __launch_bounds__(256) k_row(const int* __restrict__ Q) {
    __shared__ float acc[NN];
    __shared__ float s1[8], s2[8];
    int i = blockIdx.x;
    int t = threadIdx.x;
    for (int c = t; c < NN; c += 256) acc[c] = 0.0f;
    __syncthreads();

    int rs = g_rowstart[i], re = g_rowstart[i + 1];
    float idi = g_invd[i];
    int warp = t >> 5, lane = t & 31;
    for (int jj = rs + warp; jj < re; jj += 8) {
        int j = g_cols[jj];
        float sscale = g_cvals[jj] * idi * g_invd[j];
        int js = g_rowstart[j], je = g_rowstart[j + 1];
        for (int kk = js + lane; kk < je; kk += 32)
            atomicAdd(&acc[g_cols[kk]], sscale * g_cvals[kk]);
    }
    __syncthreads();

    float srow = 0.0f, ssq = 0.0f;
    for (int c = t; c < NN; c += 256) {
        float a = acc[c];
        srow += a;
        float dd = a - g_pi[c];
        ssq = fmaf(dd, dd, ssq);
    }
#pragma unroll
    for (int o = 16; o; o >>= 1) {
        srow += __shfl_down_sync(0xffffffffu, srow, o);
        ssq  += __shfl_down_sync(0xffffffffu, ssq, o);
    }
    if (lane == 0) { s1[warp] = srow; s2[warp] = ssq; }
    __syncthreads();
    if (t == 0) {
        float S1 = 0.0f, S2 = 0.0f;
#pragma unroll
        for (int w = 0; w < 8; w++) { S1 += s1[w]; S2 += s2[w]; }
        float pii = g_pi[i];
        atomicAdd(&g_G1, (double)pii * (double)S1);
        atomicAdd(&g_G2, (double)pii * (double)pii * (double)S2);
    }
    int qs = g_qstart[i], qe = g_qstart[i + 1];
    for (int q = qs + t; q < qe; q += 256) {
        int qq = g_qid[q];
        int j1 = idx_at(Q, 2 * qq + 1);
        g_pval[qq] = acc[j1];
    }
}

__global__ void k_final(const int* __restrict__ Q, float* __restrict__ out) {
    int q = blockIdx.x * blockDim.x + threadIdx.x;
    if (q >= EQN) return;
    double n2 = (double)NN * (double)NN;
    double sp = g_sumpi;
    double mean = (g_G1 - sp * sp) / n2;
    double var = (g_G2 - n2 * mean * mean) / (n2 - 1.0);
    double istd = rsqrt(var);
    int i = idx_at(Q, 2 * q), j = idx_at(Q, 2 * q + 1);
    double r = (double)g_pi[i] * ((double)g_pval[q] - (double)g_pi[j]);
    out[q] = (float)((r - mean) * istd);
}

// ---------------- launch ----------------
extern "C" void kernel_launch(void* const* d_in, const int* in_sizes, int n_in,
                              void* d_out, int out_size) {
    const float* X  = (const float*)d_in[0];
    const float* A  = (const float*)d_in[1];
    const float* S  = (const float*)d_in[2];
    const int*   AE = (const int*)d_in[4];
    const int*   Q  = (const int*)d_in[5];
    const float* W1 = (const float*)d_in[6];
    const float* b1 = (const float*)d_in[7];
    const float* W2 = (const float*)d_in[8];
    const float* b2 = (const float*)d_in[9];
    const float* W3 = (const float*)d_in[10];
    const float* b3 = (const float*)d_in[11];
    float* out = (float*)d_out;
    int E = in_sizes[4] / 2;
    int EB = (E + 255) / 256;
    int QB = (EQN + 255) / 256;

    k_init<<<(NN + 255) / 256, 256>>>(AE);
    k_xw_qcnt<<<128 + EQN / 128, 128>>>(X, W1, Q);
    k_mlp<<<(E + 31) / 32, 128>>>(X, AE, A, S, W1, b1, W2, b2, W3, b3, E);
    k_scan<<<1, 1024>>>();
    k_pi<<<(NN + 255) / 256, 256>>>();
    k_scatter<<<EB + QB, 256>>>(AE, Q, E, EB);
    k_row<<<NN, 256>>>(Q);
    k_final<<<(EQN + 255) / 256, 256>>>(Q, out);
}

// round 5
// speedup vs baseline: 1.3244x; 1.3244x over previous
#include <cuda_runtime.h>
#include <math.h>
#include <stdint.h>

#define NN   4096
#define DD   128
#define HH   128
#define EQN  16384
#define MAXE 131072
#define MAXNNZ 262144

// ---------------- device scratch ----------------
static __device__ float    g_vals[MAXE];
static __device__ float    g_aval[MAXE];
static __device__ float    g_d[NN];
static __device__ float    g_invd[NN];
static __device__ float    g_pi[NN];
static __device__ int      g_deg[NN];
static __device__ int      g_rowstart[NN + 1];
static __device__ int      g_rowpos[NN];
static __device__ int      g_cols[MAXNNZ];
static __device__ float    g_cvals[MAXNNZ];
static __device__ int      g_qcnt[NN];
static __device__ int      g_qstart[NN + 1];
static __device__ int      g_qpos[NN];
static __device__ int      g_qid[EQN];
static __device__ float    g_pval[EQN];
static __device__ double   g_G1, g_G2, g_sumpi;
static __device__ float    g_sumd;
static __device__ float    g_XW[NN * HH];        // X @ W1[:128,:] (fp32, exact)
static __device__ uint32_t g_W1t[HH * HH];       // tf32(W1[128:256,:])
static __device__ uint32_t g_W2t[HH * HH];       // tf32(W2)
static __device__ float    g_wd[HH];             // W3[:,1]-W3[:,0]
static __device__ int      g_is64;

__device__ __forceinline__ int idx_at(const int* __restrict__ p, int k) {
    return g_is64 ? p[2 * k] : p[k];
}
__device__ __forceinline__ uint32_t tf32r(float f) {
    uint32_t r;
    asm("cvt.rna.tf32.f32 %0, %1;" : "=r"(r) : "f"(f));
    return r;
}
__device__ __forceinline__ void mma_tf32(float* d,
                                         uint32_t a0, uint32_t a1, uint32_t a2, uint32_t a3,
                                         uint32_t b0, uint32_t b1) {
    asm("mma.sync.aligned.m16n8k8.row.col.f32.tf32.tf32.f32 "
        "{%0,%1,%2,%3}, {%4,%5,%6,%7}, {%8,%9}, {%0,%1,%2,%3};"
        : "+f"(d[0]), "+f"(d[1]), "+f"(d[2]), "+f"(d[3])
        : "r"(a0), "r"(a1), "r"(a2), "r"(a3), "r"(b0), "r"(b1));
}

// ---------------- kernels ----------------

// init + int-width detect
__global__ void k_init(const int* __restrict__ AE) {
    int i = blockIdx.x * blockDim.x + threadIdx.x;
    if (i < NN) { g_d[i] = 1.0f; g_deg[i] = 1; g_qcnt[i] = 0; }
    if (i == 0) { g_G1 = 0.0; g_G2 = 0.0; g_sumpi = 0.0; }
    if (blockIdx.x == 0) {
        __shared__ int any;
        if (threadIdx.x == 0) any = 0;
        __syncthreads();
        int loc = 0;
        for (int q = threadIdx.x; q < 1024; q += blockDim.x)
            if (AE[2 * q + 1] != 0) loc = 1;
        if (loc) atomicOr(&any, 1);
        __syncthreads();
        if (threadIdx.x == 0) g_is64 = (any == 0) ? 1 : 0;
    }
}

// pre-round weights to tf32 + head diff vector
__global__ void k_prep(const float* __restrict__ W1, const float* __restrict__ W2,
                       const float* __restrict__ W3) {
    int i = blockIdx.x * blockDim.x + threadIdx.x;
    if (i < HH * HH) {
        g_W1t[i] = tf32r(W1[(size_t)(HH + i / HH) * HH + (i % HH)]);
        g_W2t[i] = tf32r(W2[i]);
    }
    if (i < HH) g_wd[i] = W3[2 * i + 1] - W3[2 * i];
}

// XW = X @ W1[0:128, :]  (fp32, exact)
__global__ void __launch_bounds__(128) k_xw(const float* __restrict__ X,
                                            const float* __restrict__ W1) {
    __shared__ float xs[32 * 132];
    int t = threadIdx.x;
    int r0 = blockIdx.x * 32;
    int le = t >> 2, c = t & 3;
    const float* xr = X + (size_t)(r0 + le) * DD;
#pragma unroll
    for (int i = 0; i < 32; i++) { int k = c * 32 + i; xs[le * 132 + k] = xr[k]; }
    __syncthreads();
    float acc[32];
#pragma unroll
    for (int e = 0; e < 32; e++) acc[e] = 0.0f;
    for (int k = 0; k < 128; k++) {
        float w = W1[k * 128 + t];
#pragma unroll
        for (int e = 0; e < 32; e++) acc[e] = fmaf(w, xs[e * 132 + k], acc[e]);
    }
#pragma unroll
    for (int e = 0; e < 32; e++) g_XW[(size_t)(r0 + e) * 128 + t] = acc[e];
}

// ---- tensor-core edge MLP: 64 edges/block, 128 threads (4 warps x 16 rows) ----
#define AS 132
__global__ void __launch_bounds__(128) k_mlp(const float* __restrict__ X,
                                             const int* __restrict__ AE,
                                             const float* __restrict__ b1g,
                                             const float* __restrict__ b2g,
                                             const float* __restrict__ b3g,
                                             int E) {
    __shared__ __align__(16) uint32_t As[64 * AS];   // features (tf32) -> h1 (tf32)
    __shared__ int su[64], sv[64];
    int t = threadIdx.x;
    int warp = t >> 5, lane = t & 31;
    int g = lane >> 2, tig = lane & 3;
    int e0 = blockIdx.x * 64;

    // ---- feature build: |x0-x1| -> tf32, As[edge][k]
    {
        int le = t >> 1, h = t & 1;
        int e = e0 + le;
        int u = 0, v = 0;
        if (e < E) { u = idx_at(AE, 2 * e); v = idx_at(AE, 2 * e + 1); }
        if (h == 0) { su[le] = u; sv[le] = v; }
        const float4* x0 = (const float4*)(X + (size_t)u * DD + h * 64);
        const float4* x1 = (const float4*)(X + (size_t)v * DD + h * 64);
        bool ok = (e < E);
#pragma unroll
        for (int i = 0; i < 16; i++) {
            float4 a = x0[i], b = x1[i];
            uint4 w;
            w.x = tf32r(ok ? fabsf(a.x - b.x) : 0.0f);
            w.y = tf32r(ok ? fabsf(a.y - b.y) : 0.0f);
            w.z = tf32r(ok ? fabsf(a.z - b.z) : 0.0f);
            w.w = tf32r(ok ? fabsf(a.w - b.w) : 0.0f);
            *(uint4*)&As[le * AS + h * 64 + 4 * i] = w;
        }
    }
    __syncthreads();

    int r0 = warp * 16 + g, r1 = r0 + 8;
    float acc[16][4];

    // ---- layer 1 init: b1 + XW[u] + XW[v]  (full fp32)
    {
        int u0 = su[r0], v0 = sv[r0], u1 = su[r1], v1 = sv[r1];
#pragma unroll
        for (int nt = 0; nt < 16; nt++) {
            int c = 8 * nt + 2 * tig;
            float2 bb  = *(const float2*)&b1g[c];
            float2 xu0 = *(const float2*)&g_XW[(size_t)u0 * 128 + c];
            float2 xv0 = *(const float2*)&g_XW[(size_t)v0 * 128 + c];
            float2 xu1 = *(const float2*)&g_XW[(size_t)u1 * 128 + c];
            float2 xv1 = *(const float2*)&g_XW[(size_t)v1 * 128 + c];
            acc[nt][0] = bb.x + xu0.x + xv0.x;
            acc[nt][1] = bb.y + xu0.y + xv0.y;
            acc[nt][2] = bb.x + xu1.x + xv1.x;
            acc[nt][3] = bb.y + xu1.y + xv1.y;
        }
    }
    // ---- layer 1 mma
#pragma unroll
    for (int kt = 0; kt < 16; kt++) {
        int kc = kt * 8 + tig;
        uint32_t a0 = As[r0 * AS + kc];
        uint32_t a1 = As[r1 * AS + kc];
        uint32_t a2 = As[r0 * AS + kc + 4];
        uint32_t a3 = As[r1 * AS + kc + 4];
        const uint32_t* Wp = g_W1t + (size_t)kc * 128;
#pragma unroll
        for (int nt = 0; nt < 16; nt++) {
            uint32_t wb0 = Wp[nt * 8 + g];
            uint32_t wb1 = Wp[4 * 128 + nt * 8 + g];
            mma_tf32(acc[nt], a0, a1, a2, a3, wb0, wb1);
        }
    }
    __syncthreads();
    // relu -> h1 (tf32) back into As
#pragma unroll
    for (int nt = 0; nt < 16; nt++) {
        int c = 8 * nt + 2 * tig;
        As[r0 * AS + c]     = tf32r(fmaxf(acc[nt][0], 0.0f));
        As[r0 * AS + c + 1] = tf32r(fmaxf(acc[nt][1], 0.0f));
        As[r1 * AS + c]     = tf32r(fmaxf(acc[nt][2], 0.0f));
        As[r1 * AS + c + 1] = tf32r(fmaxf(acc[nt][3], 0.0f));
    }
    __syncthreads();

    // ---- layer 2 init: b2
#pragma unroll
    for (int nt = 0; nt < 16; nt++) {
        int c = 8 * nt + 2 * tig;
        float2 bb = *(const float2*)&b2g[c];
        acc[nt][0] = bb.x; acc[nt][1] = bb.y;
        acc[nt][2] = bb.x; acc[nt][3] = bb.y;
    }
    // ---- layer 2 mma
#pragma unroll
    for (int kt = 0; kt < 16; kt++) {
        int kc = kt * 8 + tig;
        uint32_t a0 = As[r0 * AS + kc];
        uint32_t a1 = As[r1 * AS + kc];
        uint32_t a2 = As[r0 * AS + kc + 4];
        uint32_t a3 = As[r1 * AS + kc + 4];
        const uint32_t* Wp = g_W2t + (size_t)kc * 128;
#pragma unroll
        for (int nt = 0; nt < 16; nt++) {
            uint32_t wb0 = Wp[nt * 8 + g];
            uint32_t wb1 = Wp[4 * 128 + nt * 8 + g];
            mma_tf32(acc[nt], a0, a1, a2, a3, wb0, wb1);
        }
    }

    // ---- head: z = relu(h2) . wd, reduce over tig lanes
    float zlo = 0.0f, zhi = 0.0f;
#pragma unroll
    for (int nt = 0; nt < 16; nt++) {
        int c = 8 * nt + 2 * tig;
        float2 w2 = *(const float2*)&g_wd[c];
        zlo = fmaf(fmaxf(acc[nt][0], 0.0f), w2.x, zlo);
        zlo = fmaf(fmaxf(acc[nt][1], 0.0f), w2.y, zlo);
        zhi = fmaf(fmaxf(acc[nt][2], 0.0f), w2.x, zhi);
        zhi = fmaf(fmaxf(acc[nt][3], 0.0f), w2.y, zhi);
    }
    zlo += __shfl_xor_sync(0xffffffffu, zlo, 1);
    zlo += __shfl_xor_sync(0xffffffffu, zlo, 2);
    zhi += __shfl_xor_sync(0xffffffffu, zhi, 1);
    zhi += __shfl_xor_sync(0xffffffffu, zhi, 2);
    if (tig == 0) {
        float zb = b3g[1] - b3g[0];
        int ea = e0 + r0;
        if (ea < E) g_vals[ea] = 1.0f / (1.0f + __expf(-(zlo + zb)));
        int eb = e0 + r1;
        if (eb < E) g_vals[eb] = 1.0f / (1.0f + __expf(-(zhi + zb)));
    }
}

// fused: edge A_enh accumulation + query row counts
__global__ void k_edge_qcnt(const float* __restrict__ A, const float* __restrict__ S,
                            const int* __restrict__ AE, const int* __restrict__ Q,
                            int E, int EB) {
    if ((int)blockIdx.x < EB) {
        int e = blockIdx.x * 256 + threadIdx.x;
        if (e >= E) return;
        int u = idx_at(AE, 2 * e), v = idx_at(AE, 2 * e + 1);
        size_t idx = ((size_t)u << 12) + (size_t)v;
        float a = 0.5f * A[idx] + 0.25f * g_vals[e] + 0.25f * S[idx];
        g_aval[e] = a;
        atomicAdd(&g_d[u], a);
        atomicAdd(&g_d[v], a);
        atomicAdd(&g_deg[u], 1);
        atomicAdd(&g_deg[v], 1);
    } else {
        int q = (blockIdx.x - EB) * 256 + threadIdx.x;
        if (q >= EQN) return;
        atomicAdd(&g_qcnt[idx_at(Q, 2 * q)], 1);
    }
}

__global__ void __launch_bounds__(1024) k_scan() {
    __shared__ int sm[1024];
    __shared__ float sf[1024];
    int t = threadIdx.x;
    int v[4];

    int s = 0;
#pragma unroll
    for (int j = 0; j < 4; j++) { v[j] = g_deg[4 * t + j]; s += v[j]; }
    sm[t] = s;
    __syncthreads();
    for (int off = 1; off < 1024; off <<= 1) {
        int x = (t >= off) ? sm[t - off] : 0;
        __syncthreads();
        sm[t] += x;
        __syncthreads();
    }
    {
        int run = sm[t] - s;
#pragma unroll
        for (int j = 0; j < 4; j++) { g_rowstart[4 * t + j] = run; g_rowpos[4 * t + j] = run; run += v[j]; }
        if (t == 1023) g_rowstart[NN] = sm[1023];
    }
    __syncthreads();

    s = 0;
#pragma unroll
    for (int j = 0; j < 4; j++) { v[j] = g_qcnt[4 * t + j]; s += v[j]; }
    sm[t] = s;
    __syncthreads();
    for (int off = 1; off < 1024; off <<= 1) {
        int x = (t >= off) ? sm[t - off] : 0;
        __syncthreads();
        sm[t] += x;
        __syncthreads();
    }
    {
        int run = sm[t] - s;
#pragma unroll
        for (int j = 0; j < 4; j++) { g_qstart[4 * t + j] = run; g_qpos[4 * t + j] = run; run += v[j]; }
        if (t == 1023) g_qstart[NN] = sm[1023];
    }
    __syncthreads();

    float fs = 0.0f;
#pragma unroll
    for (int j = 0; j < 4; j++) fs += g_d[4 * t + j];
    sf[t] = fs;
    __syncthreads();
    for (int off = 512; off; off >>= 1) {
        if (t < off) sf[t] += sf[t + off];
        __syncthreads();
    }
    if (t == 0) g_sumd = sf[0];
}

__global__ void k_pi() {
    int i = blockIdx.x * blockDim.x + threadIdx.x;
    if (i >= NN) return;
    float di = g_d[i];
    float p = di / g_sumd;
    g_pi[i] = p;
    g_invd[i] = 1.0f / di;
    atomicAdd(&g_sumpi, (double)p);
    int idx = atomicAdd(&g_rowpos[i], 1);
    g_cols[idx] = i;
    g_cvals[idx] = 1.0f;
}

// fused: CSR scatter + query-id scatter
__global__ void k_scatter(const int* __restrict__ AE, const int* __restrict__ Q,
                          int E, int EB) {
    if ((int)blockIdx.x < EB) {
        int e = blockIdx.x * 256 + threadIdx.x;
        if (e >= E) return;
        int u = idx_at(AE, 2 * e), v = idx_at(AE, 2 * e + 1);
        float a = g_aval[e];
        int i1 = atomicAdd(&g_rowpos[u], 1); g_cols[i1] = v; g_cvals[i1] = a;
        int i2 = atomicAdd(&g_rowpos[v], 1); g_cols[i2] = u; g_cvals[i2] = a;
    } else {
        int q = (blockIdx.x - EB) * 256 + threadIdx.x;
        if (q >= EQN) return;
        int i = idx_at(Q, 2 * q);
        int idx = atomicAdd(&g_qpos[i], 1);
        g_qid[idx] = q;
    }
}

__global__ void __launch_bounds__(256) k_row(const int* __restrict__ Q) {
    __shared__ float acc[NN];
    __shared__ float s1[8], s2[8];
    int i = blockIdx.x;
    int t = threadIdx.x;
    for (int c = t; c < NN; c += 256) acc[c] = 0.0f;
    __syncthreads();

    int rs = g_rowstart[i], re = g_rowstart[i + 1];
    float idi = g_invd[i];
    int warp = t >> 5, lane = t & 31;
    for (int jj = rs + warp; jj < re; jj += 8) {
        int j = g_cols[jj];
        float sscale = g_cvals[jj] * idi * g_invd[j];
        int js = g_rowstart[j], je = g_rowstart[j + 1];
        for (int kk = js + lane; kk < je; kk += 32)
            atomicAdd(&acc[g_cols[kk]], sscale * g_cvals[kk]);
    }
    __syncthreads();

    float srow = 0.0f, ssq = 0.0f;
    for (int c = t; c < NN; c += 256) {
        float a = acc[c];
        srow += a;
        float dd = a - g_pi[c];
        ssq = fmaf(dd, dd, ssq);
    }
#pragma unroll
    for (int o = 16; o; o >>= 1) {
        srow += __shfl_down_sync(0xffffffffu, srow, o);
        ssq  += __shfl_down_sync(0xffffffffu, ssq, o);
    }
    if (lane == 0) { s1[warp] = srow; s2[warp] = ssq; }
    __syncthreads();
    if (t == 0) {
        float S1 = 0.0f, S2 = 0.0f;
#pragma unroll
        for (int w = 0; w < 8; w++) { S1 += s1[w]; S2 += s2[w]; }
        float pii = g_pi[i];
        atomicAdd(&g_G1, (double)pii * (double)S1);
        atomicAdd(&g_G2, (double)pii * (double)pii * (double)S2);
    }
    int qs = g_qstart[i], qe = g_qstart[i + 1];
    for (int q = qs + t; q < qe; q += 256) {
        int qq = g_qid[q];
        int j1 = idx_at(Q, 2 * qq + 1);
        g_pval[qq] = acc[j1];
    }
}

__global__ void k_final(const int* __restrict__ Q, float* __restrict__ out) {
    int q = blockIdx.x * blockDim.x + threadIdx.x;
    if (q >= EQN) return;
    double n2 = (double)NN * (double)NN;
    double sp = g_sumpi;
    double mean = (g_G1 - sp * sp) / n2;
    double var = (g_G2 - n2 * mean * mean) / (n2 - 1.0);
    double istd = rsqrt(var);
    int i = idx_at(Q, 2 * q), j = idx_at(Q, 2 * q + 1);
    double r = (double)g_pi[i] * ((double)g_pval[q] - (double)g_pi[j]);
    out[q] = (float)((r - mean) * istd);
}

// ---------------- launch ----------------
extern "C" void kernel_launch(void* const* d_in, const int* in_sizes, int n_in,
                              void* d_out, int out_size) {
    const float* X  = (const float*)d_in[0];
    const float* A  = (const float*)d_in[1];
    const float* S  = (const float*)d_in[2];
    const int*   AE = (const int*)d_in[4];
    const int*   Q  = (const int*)d_in[5];
    const float* W1 = (const float*)d_in[6];
    const float* b1 = (const float*)d_in[7];
    const float* W2 = (const float*)d_in[8];
    const float* b2 = (const float*)d_in[9];
    const float* W3 = (const float*)d_in[10];
    const float* b3 = (const float*)d_in[11];
    float* out = (float*)d_out;
    int E = in_sizes[4] / 2;
    int EB = (E + 255) / 256;
    int QB = (EQN + 255) / 256;

    k_init<<<(NN + 255) / 256, 256>>>(AE);
    k_prep<<<(HH * HH + 255) / 256, 256>>>(W1, W2, W3);
    k_xw<<<NN / 32, 128>>>(X, W1);
    k_mlp<<<(E + 63) / 64, 128>>>(X, AE, b1, b2, b3, E);
    k_edge_qcnt<<<EB + QB, 256>>>(A, S, AE, Q, E, EB);
    k_scan<<<1, 1024>>>();
    k_pi<<<(NN + 255) / 256, 256>>>();
    k_scatter<<<EB + QB, 256>>>(AE, Q, E, EB);
    k_row<<<NN, 256>>>(Q);
    k_final<<<(EQN + 255) / 256, 256>>>(Q, out);
}

// round 6
// speedup vs baseline: 1.7396x; 1.3135x over previous
#include <cuda_runtime.h>
#include <math.h>
#include <stdint.h>

#define NN   4096
#define DD   128
#define HH   128
#define EQN  16384
#define MAXE 131072
#define MAXNNZ 262144

// ---------------- device scratch ----------------
static __device__ float    g_vals[MAXE];
static __device__ float    g_aval[MAXE];
static __device__ float    g_d[NN];
static __device__ float    g_invd[NN];
static __device__ float    g_pi[NN];
static __device__ int      g_deg[NN];
static __device__ int      g_rowstart[NN + 1];
static __device__ int      g_rowpos[NN];
static __device__ int      g_cols[MAXNNZ];
static __device__ float    g_cvals[MAXNNZ];
static __device__ int      g_qcnt[NN];
static __device__ int      g_qstart[NN + 1];
static __device__ int      g_qpos[NN];
static __device__ int      g_qid[EQN];
static __device__ float    g_pval[EQN];
static __device__ double   g_G1, g_G2, g_sumpi;
static __device__ float    g_sumd;
static __device__ float    g_XW[NN * HH];        // X @ W1[:128,:] (fp32, exact)
static __device__ uint32_t g_W1p[HH * HH];       // frag-packed tf32(W1[128:256,:])
static __device__ uint32_t g_W2p[HH * HH];       // frag-packed tf32(W2)
static __device__ float    g_wd[HH];             // W3[:,1]-W3[:,0]
static __device__ int      g_is64;

__device__ __forceinline__ int idx_at(const int* __restrict__ p, int k) {
    return g_is64 ? p[2 * k] : p[k];
}
__device__ __forceinline__ uint32_t tf32r(float f) {
    uint32_t r;
    asm("cvt.rna.tf32.f32 %0, %1;" : "=r"(r) : "f"(f));
    return r;
}
__device__ __forceinline__ void mma_tf32(float* d, const uint32_t* a,
                                         uint32_t b0, uint32_t b1) {
    asm("mma.sync.aligned.m16n8k8.row.col.f32.tf32.tf32.f32 "
        "{%0,%1,%2,%3}, {%4,%5,%6,%7}, {%8,%9}, {%0,%1,%2,%3};"
        : "+f"(d[0]), "+f"(d[1]), "+f"(d[2]), "+f"(d[3])
        : "r"(a[0]), "r"(a[1]), "r"(a[2]), "r"(a[3]), "r"(b0), "r"(b1));
}

// ---------------- kernels ----------------

// init + int-width detect
__global__ void k_init(const int* __restrict__ AE) {
    int i = blockIdx.x * blockDim.x + threadIdx.x;
    if (i < NN) { g_d[i] = 1.0f; g_deg[i] = 1; g_qcnt[i] = 0; }
    if (i == 0) { g_G1 = 0.0; g_G2 = 0.0; g_sumpi = 0.0; }
    if (blockIdx.x == 0) {
        __shared__ int any;
        if (threadIdx.x == 0) any = 0;
        __syncthreads();
        int loc = 0;
        for (int q = threadIdx.x; q < 1024; q += blockDim.x)
            if (AE[2 * q + 1] != 0) loc = 1;
        if (loc) atomicOr(&any, 1);
        __syncthreads();
        if (threadIdx.x == 0) g_is64 = (any == 0) ? 1 : 0;
    }
}

// pack weights into MMA-fragment order:
// f = kt*1024 + tig*256 + g*32 + 2*nt + which  ->  W[k= kt*8+tig+4*which][n= nt*8+g]
__global__ void k_prep(const float* __restrict__ W1, const float* __restrict__ W2,
                       const float* __restrict__ W3) {
    int i = blockIdx.x * blockDim.x + threadIdx.x;
    if (i < HH * HH) {
        int which = i & 1;
        int nt  = (i >> 1) & 15;
        int g   = (i >> 5) & 7;
        int tig = (i >> 8) & 3;
        int kt  = i >> 10;
        int k = kt * 8 + tig + 4 * which;
        int n = nt * 8 + g;
        g_W1p[i] = tf32r(W1[(size_t)(HH + k) * HH + n]);
        g_W2p[i] = tf32r(W2[(size_t)k * HH + n]);
    }
    if (i < HH) g_wd[i] = W3[2 * i + 1] - W3[2 * i];
}

// XW = X @ W1[0:128, :]  (fp32, exact)
__global__ void __launch_bounds__(128) k_xw(const float* __restrict__ X,
                                            const float* __restrict__ W1) {
    __shared__ float xs[32 * 132];
    int t = threadIdx.x;
    int r0 = blockIdx.x * 32;
    int le = t >> 2, c = t & 3;
    const float* xr = X + (size_t)(r0 + le) * DD;
#pragma unroll
    for (int i = 0; i < 32; i++) { int k = c * 32 + i; xs[le * 132 + k] = xr[k]; }
    __syncthreads();
    float acc[32];
#pragma unroll
    for (int e = 0; e < 32; e++) acc[e] = 0.0f;
    for (int k = 0; k < 128; k++) {
        float w = W1[k * 128 + t];
#pragma unroll
        for (int e = 0; e < 32; e++) acc[e] = fmaf(w, xs[e * 132 + k], acc[e]);
    }
#pragma unroll
    for (int e = 0; e < 32; e++) g_XW[(size_t)(r0 + e) * 128 + t] = acc[e];
}

// ---- tensor-core edge MLP, N-split warps ----
// 64 edges/block, 128 threads. Warp w owns output cols [32w,32w+32) for ALL 64 edges.
#define AS 132
__global__ void __launch_bounds__(128) k_mlp(const float* __restrict__ X,
                                             const int* __restrict__ AE,
                                             const float* __restrict__ b1g,
                                             const float* __restrict__ b2g,
                                             const float* __restrict__ b3g,
                                             int E) {
    __shared__ __align__(16) uint32_t As[64 * AS];   // features (tf32) -> h1 (tf32)
    __shared__ int   su[64], sv[64];
    __shared__ float zsm[64 * 4];
    int t = threadIdx.x;
    int w = t >> 5, lane = t & 31;
    int g = lane >> 2, tig = lane & 3;
    int e0 = blockIdx.x * 64;

    // ---- edge indices: warp w covers edges [16w,16w+16)
    if (lane < 16) {
        int le = w * 16 + lane;
        int e = e0 + le;
        int u = 0, v = 0;
        if (e < E) { u = idx_at(AE, 2 * e); v = idx_at(AE, 2 * e + 1); }
        su[le] = u; sv[le] = v;
    }
    __syncwarp();

    // ---- feature build: whole warp loads one X row per instruction (coalesced)
#pragma unroll 4
    for (int i = 0; i < 16; i++) {
        int le = w * 16 + i;
        float4 xu = ((const float4*)(X + (size_t)su[le] * DD))[lane];
        float4 xv = ((const float4*)(X + (size_t)sv[le] * DD))[lane];
        uint4 f;
        f.x = tf32r(fabsf(xu.x - xv.x));
        f.y = tf32r(fabsf(xu.y - xv.y));
        f.z = tf32r(fabsf(xu.z - xv.z));
        f.w = tf32r(fabsf(xu.w - xv.w));
        *(uint4*)&As[le * AS + 4 * lane] = f;
    }
    __syncthreads();

    float acc[4][4][4];   // [m-tile][n-subtile j][frag]

    // ---- layer 1 init: b1 + XW[u] + XW[v]  (fp32 exact)
    {
        float2 bb[4];
#pragma unroll
        for (int j = 0; j < 4; j++) bb[j] = *(const float2*)&b1g[32 * w + 8 * j + 2 * tig];
#pragma unroll
        for (int mt = 0; mt < 4; mt++) {
            int r0 = mt * 16 + g, r1 = r0 + 8;
            int u0 = su[r0], v0 = sv[r0], u1 = su[r1], v1 = sv[r1];
#pragma unroll
            for (int j = 0; j < 4; j++) {
                int c = 32 * w + 8 * j + 2 * tig;
                float2 xu0 = *(const float2*)&g_XW[(size_t)u0 * 128 + c];
                float2 xv0 = *(const float2*)&g_XW[(size_t)v0 * 128 + c];
                float2 xu1 = *(const float2*)&g_XW[(size_t)u1 * 128 + c];
                float2 xv1 = *(const float2*)&g_XW[(size_t)v1 * 128 + c];
                acc[mt][j][0] = bb[j].x + xu0.x + xv0.x;
                acc[mt][j][1] = bb[j].y + xu0.y + xv0.y;
                acc[mt][j][2] = bb[j].x + xu1.x + xv1.x;
                acc[mt][j][3] = bb[j].y + xu1.y + xv1.y;
            }
        }
    }

    // ---- layer 1 mma
#pragma unroll
    for (int kt = 0; kt < 16; kt++) {
        int kc = kt * 8 + tig;
        uint32_t a[4][4];
#pragma unroll
        for (int mt = 0; mt < 4; mt++) {
            int r0 = mt * 16 + g;
            a[mt][0] = As[r0 * AS + kc];
            a[mt][1] = As[(r0 + 8) * AS + kc];
            a[mt][2] = As[r0 * AS + kc + 4];
            a[mt][3] = As[(r0 + 8) * AS + kc + 4];
        }
        const uint4* Wp = (const uint4*)(g_W1p + (((kt * 4 + tig) * 8 + g) << 5));
        uint4 wA = Wp[2 * w], wB = Wp[2 * w + 1];
#pragma unroll
        for (int mt = 0; mt < 4; mt++) {
            mma_tf32(acc[mt][0], a[mt], wA.x, wA.y);
            mma_tf32(acc[mt][1], a[mt], wA.z, wA.w);
            mma_tf32(acc[mt][2], a[mt], wB.x, wB.y);
            mma_tf32(acc[mt][3], a[mt], wB.z, wB.w);
        }
    }
    __syncthreads();   // all warps done reading features

    // relu -> h1 (tf32) back into As
#pragma unroll
    for (int mt = 0; mt < 4; mt++) {
        int r0 = mt * 16 + g;
#pragma unroll
        for (int j = 0; j < 4; j++) {
            int c = 32 * w + 8 * j + 2 * tig;
            uint2 p0, p1;
            p0.x = tf32r(fmaxf(acc[mt][j][0], 0.0f));
            p0.y = tf32r(fmaxf(acc[mt][j][1], 0.0f));
            p1.x = tf32r(fmaxf(acc[mt][j][2], 0.0f));
            p1.y = tf32r(fmaxf(acc[mt][j][3], 0.0f));
            *(uint2*)&As[r0 * AS + c] = p0;
            *(uint2*)&As[(r0 + 8) * AS + c] = p1;
        }
    }
    __syncthreads();

    // ---- layer 2 init: b2
    {
#pragma unroll
        for (int j = 0; j < 4; j++) {
            float2 bb = *(const float2*)&b2g[32 * w + 8 * j + 2 * tig];
#pragma unroll
            for (int mt = 0; mt < 4; mt++) {
                acc[mt][j][0] = bb.x; acc[mt][j][1] = bb.y;
                acc[mt][j][2] = bb.x; acc[mt][j][3] = bb.y;
            }
        }
    }
    // ---- layer 2 mma
#pragma unroll
    for (int kt = 0; kt < 16; kt++) {
        int kc = kt * 8 + tig;
        uint32_t a[4][4];
#pragma unroll
        for (int mt = 0; mt < 4; mt++) {
            int r0 = mt * 16 + g;
            a[mt][0] = As[r0 * AS + kc];
            a[mt][1] = As[(r0 + 8) * AS + kc];
            a[mt][2] = As[r0 * AS + kc + 4];
            a[mt][3] = As[(r0 + 8) * AS + kc + 4];
        }
        const uint4* Wp = (const uint4*)(g_W2p + (((kt * 4 + tig) * 8 + g) << 5));
        uint4 wA = Wp[2 * w], wB = Wp[2 * w + 1];
#pragma unroll
        for (int mt = 0; mt < 4; mt++) {
            mma_tf32(acc[mt][0], a[mt], wA.x, wA.y);
            mma_tf32(acc[mt][1], a[mt], wA.z, wA.w);
            mma_tf32(acc[mt][2], a[mt], wB.x, wB.y);
            mma_tf32(acc[mt][3], a[mt], wB.z, wB.w);
        }
    }

    // ---- head: z = relu(h2) . wd  (partial over this warp's 32 cols)
    float z[4][2];
#pragma unroll
    for (int mt = 0; mt < 4; mt++) { z[mt][0] = 0.0f; z[mt][1] = 0.0f; }
    {
        float2 wdj[4];
#pragma unroll
        for (int j = 0; j < 4; j++) wdj[j] = *(const float2*)&g_wd[32 * w + 8 * j + 2 * tig];
#pragma unroll
        for (int mt = 0; mt < 4; mt++)
#pragma unroll
            for (int j = 0; j < 4; j++) {
                z[mt][0] = fmaf(fmaxf(acc[mt][j][0], 0.0f), wdj[j].x,
                           fmaf(fmaxf(acc[mt][j][1], 0.0f), wdj[j].y, z[mt][0]));
                z[mt][1] = fmaf(fmaxf(acc[mt][j][2], 0.0f), wdj[j].x,
                           fmaf(fmaxf(acc[mt][j][3], 0.0f), wdj[j].y, z[mt][1]));
            }
    }
#pragma unroll
    for (int mt = 0; mt < 4; mt++)
#pragma unroll
        for (int h = 0; h < 2; h++) {
            z[mt][h] += __shfl_xor_sync(0xffffffffu, z[mt][h], 1);
            z[mt][h] += __shfl_xor_sync(0xffffffffu, z[mt][h], 2);
        }
    if (tig == 0) {
#pragma unroll
        for (int mt = 0; mt < 4; mt++)
#pragma unroll
            for (int h = 0; h < 2; h++)
                zsm[(mt * 16 + g + 8 * h) * 4 + w] = z[mt][h];
    }
    __syncthreads();
    if (t < 64) {
        int e = e0 + t;
        if (e < E) {
            float zz = zsm[4 * t] + zsm[4 * t + 1] + zsm[4 * t + 2] + zsm[4 * t + 3]
                     + (b3g[1] - b3g[0]);
            g_vals[e] = 1.0f / (1.0f + __expf(-zz));
        }
    }
}

// fused: edge A_enh accumulation + query row counts
__global__ void k_edge_qcnt(const float* __restrict__ A, const float* __restrict__ S,
                            const int* __restrict__ AE, const int* __restrict__ Q,
                            int E, int EB) {
    if ((int)blockIdx.x < EB) {
        int e = blockIdx.x * 256 + threadIdx.x;
        if (e >= E) return;
        int u = idx_at(AE, 2 * e), v = idx_at(AE, 2 * e + 1);
        size_t idx = ((size_t)u << 12) + (size_t)v;
        float a = 0.5f * A[idx] + 0.25f * g_vals[e] + 0.25f * S[idx];
        g_aval[e] = a;
        atomicAdd(&g_d[u], a);
        atomicAdd(&g_d[v], a);
        atomicAdd(&g_deg[u], 1);
        atomicAdd(&g_deg[v], 1);
    } else {
        int q = (blockIdx.x - EB) * 256 + threadIdx.x;
        if (q >= EQN) return;
        atomicAdd(&g_qcnt[idx_at(Q, 2 * q)], 1);
    }
}

__global__ void __launch_bounds__(1024) k_scan() {
    __shared__ int sm[1024];
    __shared__ float sf[1024];
    int t = threadIdx.x;
    int v[4];

    int s = 0;
#pragma unroll
    for (int j = 0; j < 4; j++) { v[j] = g_deg[4 * t + j]; s += v[j]; }
    sm[t] = s;
    __syncthreads();
    for (int off = 1; off < 1024; off <<= 1) {
        int x = (t >= off) ? sm[t - off] : 0;
        __syncthreads();
        sm[t] += x;
        __syncthreads();
    }
    {
        int run = sm[t] - s;
#pragma unroll
        for (int j = 0; j < 4; j++) { g_rowstart[4 * t + j] = run; g_rowpos[4 * t + j] = run; run += v[j]; }
        if (t == 1023) g_rowstart[NN] = sm[1023];
    }
    __syncthreads();

    s = 0;
#pragma unroll
    for (int j = 0; j < 4; j++) { v[j] = g_qcnt[4 * t + j]; s += v[j]; }
    sm[t] = s;
    __syncthreads();
    for (int off = 1; off < 1024; off <<= 1) {
        int x = (t >= off) ? sm[t - off] : 0;
        __syncthreads();
        sm[t] += x;
        __syncthreads();
    }
    {
        int run = sm[t] - s;
#pragma unroll
        for (int j = 0; j < 4; j++) { g_qstart[4 * t + j] = run; g_qpos[4 * t + j] = run; run += v[j]; }
        if (t == 1023) g_qstart[NN] = sm[1023];
    }
    __syncthreads();

    float fs = 0.0f;
#pragma unroll
    for (int j = 0; j < 4; j++) fs += g_d[4 * t + j];
    sf[t] = fs;
    __syncthreads();
    for (int off = 512; off; off >>= 1) {
        if (t < off) sf[t] += sf[t + off];
        __syncthreads();
    }
    if (t == 0) g_sumd = sf[0];
}

__global__ void k_pi() {
    int i = blockIdx.x * blockDim.x + threadIdx.x;
    if (i >= NN) return;
    float di = g_d[i];
    float p = di / g_sumd;
    g_pi[i] = p;
    g_invd[i] = 1.0f / di;
    atomicAdd(&g_sumpi, (double)p);
    int idx = atomicAdd(&g_rowpos[i], 1);
    g_cols[idx] = i;
    g_cvals[idx] = 1.0f;
}

// fused: CSR scatter + query-id scatter
__global__ void k_scatter(const int* __restrict__ AE, const int* __restrict__ Q,
                          int E, int EB) {
    if ((int)blockIdx.x < EB) {
        int e = blockIdx.x * 256 + threadIdx.x;
        if (e >= E) return;
        int u = idx_at(AE, 2 * e), v = idx_at(AE, 2 * e + 1);
        float a = g_aval[e];
        int i1 = atomicAdd(&g_rowpos[u], 1); g_cols[i1] = v; g_cvals[i1] = a;
        int i2 = atomicAdd(&g_rowpos[v], 1); g_cols[i2] = u; g_cvals[i2] = a;
    } else {
        int q = (blockIdx.x - EB) * 256 + threadIdx.x;
        if (q >= EQN) return;
        int i = idx_at(Q, 2 * q);
        int idx = atomicAdd(&g_qpos[i], 1);
        g_qid[idx] = q;
    }
}

__global__ void __launch_bounds__(256) k_row(const int* __restrict__ Q) {
    __shared__ float acc[NN];
    __shared__ float s1[8], s2[8];
    int i = blockIdx.x;
    int t = threadIdx.x;
    for (int c = t; c < NN; c += 256) acc[c] = 0.0f;
    __syncthreads();

    int rs = g_rowstart[i], re = g_rowstart[i + 1];
    float idi = g_invd[i];
    int warp = t >> 5, lane = t & 31;
    for (int jj = rs + warp; jj < re; jj += 8) {
        int j = g_cols[jj];
        float sscale = g_cvals[jj] * idi * g_invd[j];
        int js = g_rowstart[j], je = g_rowstart[j + 1];
        for (int kk = js + lane; kk < je; kk += 32)
            atomicAdd(&acc[g_cols[kk]], sscale * g_cvals[kk]);
    }
    __syncthreads();

    float srow = 0.0f, ssq = 0.0f;
    for (int c = t; c < NN; c += 256) {
        float a = acc[c];
        srow += a;
        float dd = a - g_pi[c];
        ssq = fmaf(dd, dd, ssq);
    }
#pragma unroll
    for (int o = 16; o; o >>= 1) {
        srow += __shfl_down_sync(0xffffffffu, srow, o);
        ssq  += __shfl_down_sync(0xffffffffu, ssq, o);
    }
    if (lane == 0) { s1[warp] = srow; s2[warp] = ssq; }
    __syncthreads();
    if (t == 0) {
        float S1 = 0.0f, S2 = 0.0f;
#pragma unroll
        for (int w2 = 0; w2 < 8; w2++) { S1 += s1[w2]; S2 += s2[w2]; }
        float pii = g_pi[i];
        atomicAdd(&g_G1, (double)pii * (double)S1);
        atomicAdd(&g_G2, (double)pii * (double)pii * (double)S2);
    }
    int qs = g_qstart[i], qe = g_qstart[i + 1];
    for (int q = qs + t; q < qe; q += 256) {
        int qq = g_qid[q];
        int j1 = idx_at(Q, 2 * qq + 1);
        g_pval[qq] = acc[j1];
    }
}

__global__ void k_final(const int* __restrict__ Q, float* __restrict__ out) {
    int q = blockIdx.x * blockDim.x + threadIdx.x;
    if (q >= EQN) return;
    double n2 = (double)NN * (double)NN;
    double sp = g_sumpi;
    double mean = (g_G1 - sp * sp) / n2;
    double var = (g_G2 - n2 * mean * mean) / (n2 - 1.0);
    double istd = rsqrt(var);
    int i = idx_at(Q, 2 * q), j = idx_at(Q, 2 * q + 1);
    double r = (double)g_pi[i] * ((double)g_pval[q] - (double)g_pi[j]);
    out[q] = (float)((r - mean) * istd);
}

// ---------------- launch ----------------
extern "C" void kernel_launch(void* const* d_in, const int* in_sizes, int n_in,
                              void* d_out, int out_size) {
    const float* X  = (const float*)d_in[0];
    const float* A  = (const float*)d_in[1];
    const float* S  = (const float*)d_in[2];
    const int*   AE = (const int*)d_in[4];
    const int*   Q  = (const int*)d_in[5];
    const float* W1 = (const float*)d_in[6];
    const float* b1 = (const float*)d_in[7];
    const float* W2 = (const float*)d_in[8];
    const float* b2 = (const float*)d_in[9];
    const float* W3 = (const float*)d_in[10];
    const float* b3 = (const float*)d_in[11];
    float* out = (float*)d_out;
    int E = in_sizes[4] / 2;
    int EB = (E + 255) / 256;
    int QB = (EQN + 255) / 256;

    k_init<<<(NN + 255) / 256, 256>>>(AE);
    k_prep<<<(HH * HH + 255) / 256, 256>>>(W1, W2, W3);
    k_xw<<<NN / 32, 128>>>(X, W1);
    k_mlp<<<(E + 63) / 64, 128>>>(X, AE, b1, b2, b3, E);
    k_edge_qcnt<<<EB + QB, 256>>>(A, S, AE, Q, E, EB);
    k_scan<<<1, 1024>>>();
    k_pi<<<(NN + 255) / 256, 256>>>();
    k_scatter<<<EB + QB, 256>>>(AE, Q, E, EB);
    k_row<<<NN, 256>>>(Q);
    k_final<<<(EQN + 255) / 256, 256>>>(Q, out);
}

// round 7
// speedup vs baseline: 2.0867x; 1.1995x over previous
#include <cuda_runtime.h>
#include <math.h>
#include <stdint.h>

#define NN   4096
#define DD   128
#define HH   128
#define EQN  16384
#define MAXE 131072
#define MAXNNZ 262144

// ---------------- device scratch ----------------
static __device__ float    g_vals[MAXE];
static __device__ float    g_aval[MAXE];
static __device__ float    g_d[NN];
static __device__ float    g_invd[NN];
static __device__ float    g_pi[NN];
static __device__ int      g_deg[NN];
static __device__ int      g_rowstart[NN + 1];
static __device__ int      g_rowpos[NN];
static __device__ int      g_cols[MAXNNZ];
static __device__ float    g_cvals[MAXNNZ];
static __device__ int      g_qcnt[NN];
static __device__ int      g_qstart[NN + 1];
static __device__ int      g_qpos[NN];
static __device__ int      g_qid[EQN];
static __device__ float    g_pval[EQN];
static __device__ double   g_G1, g_G2, g_sumpi;
static __device__ float    g_sumd;
static __device__ float    g_XW[NN * HH];        // X @ W1[:128,:] (fp32, exact)
static __device__ uint32_t g_W1p[HH * HH];       // frag-packed tf32(W1[128:256,:]), warp-coalesced
static __device__ uint32_t g_W2p[HH * HH];       // frag-packed tf32(W2), warp-coalesced
static __device__ float    g_wd[HH];             // W3[:,1]-W3[:,0]
static __device__ int      g_is64;

__device__ __forceinline__ int idx_at(const int* __restrict__ p, int k) {
    return g_is64 ? p[2 * k] : p[k];
}
__device__ __forceinline__ uint32_t tf32r(float f) {
    uint32_t r;
    asm("cvt.rna.tf32.f32 %0, %1;" : "=r"(r) : "f"(f));
    return r;
}
__device__ __forceinline__ void mma_tf32(float* d, const uint32_t* a,
                                         uint32_t b0, uint32_t b1) {
    asm("mma.sync.aligned.m16n8k8.row.col.f32.tf32.tf32.f32 "
        "{%0,%1,%2,%3}, {%4,%5,%6,%7}, {%8,%9}, {%0,%1,%2,%3};"
        : "+f"(d[0]), "+f"(d[1]), "+f"(d[2]), "+f"(d[3])
        : "r"(a[0]), "r"(a[1]), "r"(a[2]), "r"(a[3]), "r"(b0), "r"(b1));
}

// ---------------- kernels ----------------

// init + int-width detect
__global__ void k_init(const int* __restrict__ AE) {
    int i = blockIdx.x * blockDim.x + threadIdx.x;
    if (i < NN) { g_d[i] = 1.0f; g_deg[i] = 1; g_qcnt[i] = 0; }
    if (i == 0) { g_G1 = 0.0; g_G2 = 0.0; g_sumpi = 0.0; }
    if (blockIdx.x == 0) {
        __shared__ int any;
        if (threadIdx.x == 0) any = 0;
        __syncthreads();
        int loc = 0;
        for (int q = threadIdx.x; q < 1024; q += blockDim.x)
            if (AE[2 * q + 1] != 0) loc = 1;
        if (loc) atomicOr(&any, 1);
        __syncthreads();
        if (threadIdx.x == 0) g_is64 = (any == 0) ? 1 : 0;
    }
}

// pack weights, warp-coalesced frag order:
// i = ((kt*4 + w)*32 + lane)*8 + q ; lane=4g+tig ; q=2*j+which
//   -> W[k = kt*8 + tig + 4*which][n = 32*w + 8*j + g]
__global__ void k_prep(const float* __restrict__ W1, const float* __restrict__ W2,
                       const float* __restrict__ W3) {
    int i = blockIdx.x * blockDim.x + threadIdx.x;
    if (i < HH * HH) {
        int q    = i & 7;
        int lane = (i >> 3) & 31;
        int w    = (i >> 8) & 3;
        int kt   = i >> 10;
        int tig = lane & 3, g = lane >> 2;
        int j = q >> 1, which = q & 1;
        int k = kt * 8 + tig + 4 * which;
        int n = 32 * w + 8 * j + g;
        g_W1p[i] = tf32r(W1[(size_t)(HH + k) * HH + n]);
        g_W2p[i] = tf32r(W2[(size_t)k * HH + n]);
    }
    if (i < HH) g_wd[i] = W3[2 * i + 1] - W3[2 * i];
}

// XW = X @ W1[0:128, :]  (fp32, exact)
__global__ void __launch_bounds__(128) k_xw(const float* __restrict__ X,
                                            const float* __restrict__ W1) {
    __shared__ float xs[32 * 132];
    int t = threadIdx.x;
    int r0 = blockIdx.x * 32;
    int le = t >> 2, c = t & 3;
    const float* xr = X + (size_t)(r0 + le) * DD;
#pragma unroll
    for (int i = 0; i < 32; i++) { int k = c * 32 + i; xs[le * 132 + k] = xr[k]; }
    __syncthreads();
    float acc[32];
#pragma unroll
    for (int e = 0; e < 32; e++) acc[e] = 0.0f;
    for (int k = 0; k < 128; k++) {
        float w = W1[k * 128 + t];
#pragma unroll
        for (int e = 0; e < 32; e++) acc[e] = fmaf(w, xs[e * 132 + k], acc[e]);
    }
#pragma unroll
    for (int e = 0; e < 32; e++) g_XW[(size_t)(r0 + e) * 128 + t] = acc[e];
}

// ---- tensor-core edge MLP, N-split warps, coalesced weight frags ----
#define AS 132
__global__ void __launch_bounds__(128) k_mlp(const float* __restrict__ X,
                                             const int* __restrict__ AE,
                                             const float* __restrict__ b1g,
                                             const float* __restrict__ b2g,
                                             const float* __restrict__ b3g,
                                             int E) {
    __shared__ __align__(16) uint32_t As[64 * AS];   // features (tf32) -> h1 (tf32)
    __shared__ int   su[64], sv[64];
    __shared__ float zsm[64 * 4];
    int t = threadIdx.x;
    int w = t >> 5, lane = t & 31;
    int g = lane >> 2, tig = lane & 3;
    int e0 = blockIdx.x * 64;

    // ---- edge indices: warp w covers edges [16w,16w+16)
    if (lane < 16) {
        int le = w * 16 + lane;
        int e = e0 + le;
        int u = 0, v = 0;
        if (e < E) { u = idx_at(AE, 2 * e); v = idx_at(AE, 2 * e + 1); }
        su[le] = u; sv[le] = v;
    }
    __syncwarp();

    // ---- feature build (coalesced row loads)
#pragma unroll 4
    for (int i = 0; i < 16; i++) {
        int le = w * 16 + i;
        float4 xu = ((const float4*)(X + (size_t)su[le] * DD))[lane];
        float4 xv = ((const float4*)(X + (size_t)sv[le] * DD))[lane];
        uint4 f;
        f.x = tf32r(fabsf(xu.x - xv.x));
        f.y = tf32r(fabsf(xu.y - xv.y));
        f.z = tf32r(fabsf(xu.z - xv.z));
        f.w = tf32r(fabsf(xu.w - xv.w));
        *(uint4*)&As[le * AS + 4 * lane] = f;
    }
    __syncthreads();

    float acc[4][4][4];   // [m-tile][n-subtile j][frag]

    // ---- layer 1 init: b1 + XW[u] + XW[v]  (fp32 exact)
    {
        float2 bb[4];
#pragma unroll
        for (int j = 0; j < 4; j++) bb[j] = *(const float2*)&b1g[32 * w + 8 * j + 2 * tig];
#pragma unroll
        for (int mt = 0; mt < 4; mt++) {
            int r0 = mt * 16 + g, r1 = r0 + 8;
            int u0 = su[r0], v0 = sv[r0], u1 = su[r1], v1 = sv[r1];
#pragma unroll
            for (int j = 0; j < 4; j++) {
                int c = 32 * w + 8 * j + 2 * tig;
                float2 xu0 = *(const float2*)&g_XW[(size_t)u0 * 128 + c];
                float2 xv0 = *(const float2*)&g_XW[(size_t)v0 * 128 + c];
                float2 xu1 = *(const float2*)&g_XW[(size_t)u1 * 128 + c];
                float2 xv1 = *(const float2*)&g_XW[(size_t)v1 * 128 + c];
                acc[mt][j][0] = bb[j].x + xu0.x + xv0.x;
                acc[mt][j][1] = bb[j].y + xu0.y + xv0.y;
                acc[mt][j][2] = bb[j].x + xu1.x + xv1.x;
                acc[mt][j][3] = bb[j].y + xu1.y + xv1.y;
            }
        }
    }

    // ---- layer 1 mma
#pragma unroll
    for (int kt = 0; kt < 16; kt++) {
        int kc = kt * 8 + tig;
        uint32_t a[4][4];
#pragma unroll
        for (int mt = 0; mt < 4; mt++) {
            int r0 = mt * 16 + g;
            a[mt][0] = As[r0 * AS + kc];
            a[mt][1] = As[(r0 + 8) * AS + kc];
            a[mt][2] = As[r0 * AS + kc + 4];
            a[mt][3] = As[(r0 + 8) * AS + kc + 4];
        }
        const uint4* Wp = (const uint4*)(g_W1p + (((kt * 4 + w) * 32 + lane) << 3));
        uint4 wA = Wp[0], wB = Wp[1];
#pragma unroll
        for (int mt = 0; mt < 4; mt++) {
            mma_tf32(acc[mt][0], a[mt], wA.x, wA.y);
            mma_tf32(acc[mt][1], a[mt], wA.z, wA.w);
            mma_tf32(acc[mt][2], a[mt], wB.x, wB.y);
            mma_tf32(acc[mt][3], a[mt], wB.z, wB.w);
        }
    }
    __syncthreads();   // all warps done reading features

    // relu -> h1 (tf32) back into As
#pragma unroll
    for (int mt = 0; mt < 4; mt++) {
        int r0 = mt * 16 + g;
#pragma unroll
        for (int j = 0; j < 4; j++) {
            int c = 32 * w + 8 * j + 2 * tig;
            uint2 p0, p1;
            p0.x = tf32r(fmaxf(acc[mt][j][0], 0.0f));
            p0.y = tf32r(fmaxf(acc[mt][j][1], 0.0f));
            p1.x = tf32r(fmaxf(acc[mt][j][2], 0.0f));
            p1.y = tf32r(fmaxf(acc[mt][j][3], 0.0f));
            *(uint2*)&As[r0 * AS + c] = p0;
            *(uint2*)&As[(r0 + 8) * AS + c] = p1;
        }
    }
    __syncthreads();

    // ---- layer 2 init: b2
    {
#pragma unroll
        for (int j = 0; j < 4; j++) {
            float2 bb = *(const float2*)&b2g[32 * w + 8 * j + 2 * tig];
#pragma unroll
            for (int mt = 0; mt < 4; mt++) {
                acc[mt][j][0] = bb.x; acc[mt][j][1] = bb.y;
                acc[mt][j][2] = bb.x; acc[mt][j][3] = bb.y;
            }
        }
    }
    // ---- layer 2 mma
#pragma unroll
    for (int kt = 0; kt < 16; kt++) {
        int kc = kt * 8 + tig;
        uint32_t a[4][4];
#pragma unroll
        for (int mt = 0; mt < 4; mt++) {
            int r0 = mt * 16 + g;
            a[mt][0] = As[r0 * AS + kc];
            a[mt][1] = As[(r0 + 8) * AS + kc];
            a[mt][2] = As[r0 * AS + kc + 4];
            a[mt][3] = As[(r0 + 8) * AS + kc + 4];
        }
        const uint4* Wp = (const uint4*)(g_W2p + (((kt * 4 + w) * 32 + lane) << 3));
        uint4 wA = Wp[0], wB = Wp[1];
#pragma unroll
        for (int mt = 0; mt < 4; mt++) {
            mma_tf32(acc[mt][0], a[mt], wA.x, wA.y);
            mma_tf32(acc[mt][1], a[mt], wA.z, wA.w);
            mma_tf32(acc[mt][2], a[mt], wB.x, wB.y);
            mma_tf32(acc[mt][3], a[mt], wB.z, wB.w);
        }
    }

    // ---- head: z = relu(h2) . wd  (partial over this warp's 32 cols)
    float z[4][2];
#pragma unroll
    for (int mt = 0; mt < 4; mt++) { z[mt][0] = 0.0f; z[mt][1] = 0.0f; }
    {
        float2 wdj[4];
#pragma unroll
        for (int j = 0; j < 4; j++) wdj[j] = *(const float2*)&g_wd[32 * w + 8 * j + 2 * tig];
#pragma unroll
        for (int mt = 0; mt < 4; mt++)
#pragma unroll
            for (int j = 0; j < 4; j++) {
                z[mt][0] = fmaf(fmaxf(acc[mt][j][0], 0.0f), wdj[j].x,
                           fmaf(fmaxf(acc[mt][j][1], 0.0f), wdj[j].y, z[mt][0]));
                z[mt][1] = fmaf(fmaxf(acc[mt][j][2], 0.0f), wdj[j].x,
                           fmaf(fmaxf(acc[mt][j][3], 0.0f), wdj[j].y, z[mt][1]));
            }
    }
#pragma unroll
    for (int mt = 0; mt < 4; mt++)
#pragma unroll
        for (int h = 0; h < 2; h++) {
            z[mt][h] += __shfl_xor_sync(0xffffffffu, z[mt][h], 1);
            z[mt][h] += __shfl_xor_sync(0xffffffffu, z[mt][h], 2);
        }
    if (tig == 0) {
#pragma unroll
        for (int mt = 0; mt < 4; mt++)
#pragma unroll
            for (int h = 0; h < 2; h++)
                zsm[(mt * 16 + g + 8 * h) * 4 + w] = z[mt][h];
    }
    __syncthreads();
    if (t < 64) {
        int e = e0 + t;
        if (e < E) {
            float zz = zsm[4 * t] + zsm[4 * t + 1] + zsm[4 * t + 2] + zsm[4 * t + 3]
                     + (b3g[1] - b3g[0]);
            g_vals[e] = 1.0f / (1.0f + __expf(-zz));
        }
    }
}

// fused: edge A_enh accumulation + query row counts
__global__ void k_edge_qcnt(const float* __restrict__ A, const float* __restrict__ S,
                            const int* __restrict__ AE, const int* __restrict__ Q,
                            int E, int EB) {
    if ((int)blockIdx.x < EB) {
        int e = blockIdx.x * 256 + threadIdx.x;
        if (e >= E) return;
        int u = idx_at(AE, 2 * e), v = idx_at(AE, 2 * e + 1);
        size_t idx = ((size_t)u << 12) + (size_t)v;
        float a = 0.5f * A[idx] + 0.25f * g_vals[e] + 0.25f * S[idx];
        g_aval[e] = a;
        atomicAdd(&g_d[u], a);
        atomicAdd(&g_d[v], a);
        atomicAdd(&g_deg[u], 1);
        atomicAdd(&g_deg[v], 1);
    } else {
        int q = (blockIdx.x - EB) * 256 + threadIdx.x;
        if (q >= EQN) return;
        atomicAdd(&g_qcnt[idx_at(Q, 2 * q)], 1);
    }
}

// shuffle-based scans: rows, query rows, sum(d). 1024 threads.
__global__ void __launch_bounds__(1024) k_scan() {
    __shared__ int   wsum[32];
    __shared__ float wfs[32];
    int t = threadIdx.x;
    int lane = t & 31, wid = t >> 5;

    // ---- row degree scan ----
    {
        int v[4], s = 0;
#pragma unroll
        for (int j = 0; j < 4; j++) { v[j] = g_deg[4 * t + j]; s += v[j]; }
        int incl = s;
#pragma unroll
        for (int o = 1; o < 32; o <<= 1) {
            int x = __shfl_up_sync(0xffffffffu, incl, o);
            if (lane >= o) incl += x;
        }
        if (lane == 31) wsum[wid] = incl;
        __syncthreads();
        if (wid == 0) {
            int ws = wsum[lane];
            int wi = ws;
#pragma unroll
            for (int o = 1; o < 32; o <<= 1) {
                int x = __shfl_up_sync(0xffffffffu, wi, o);
                if (lane >= o) wi += x;
            }
            wsum[lane] = wi - ws;   // exclusive
        }
        __syncthreads();
        int run = wsum[wid] + incl - s;
#pragma unroll
        for (int j = 0; j < 4; j++) { g_rowstart[4 * t + j] = run; g_rowpos[4 * t + j] = run; run += v[j]; }
        if (t == 1023) g_rowstart[NN] = run;
    }
    __syncthreads();

    // ---- query count scan ----
    {
        int v[4], s = 0;
#pragma unroll
        for (int j = 0; j < 4; j++) { v[j] = g_qcnt[4 * t + j]; s += v[j]; }
        int incl = s;
#pragma unroll
        for (int o = 1; o < 32; o <<= 1) {
            int x = __shfl_up_sync(0xffffffffu, incl, o);
            if (lane >= o) incl += x;
        }
        if (lane == 31) wsum[wid] = incl;
        __syncthreads();
        if (wid == 0) {
            int ws = wsum[lane];
            int wi = ws;
#pragma unroll
            for (int o = 1; o < 32; o <<= 1) {
                int x = __shfl_up_sync(0xffffffffu, wi, o);
                if (lane >= o) wi += x;
            }
            wsum[lane] = wi - ws;
        }
        __syncthreads();
        int run = wsum[wid] + incl - s;
#pragma unroll
        for (int j = 0; j < 4; j++) { g_qstart[4 * t + j] = run; g_qpos[4 * t + j] = run; run += v[j]; }
        if (t == 1023) g_qstart[NN] = run;
    }
    __syncthreads();

    // ---- sum(d) ----
    {
        float fs = 0.0f;
#pragma unroll
        for (int j = 0; j < 4; j++) fs += g_d[4 * t + j];
#pragma unroll
        for (int o = 16; o; o >>= 1) fs += __shfl_xor_sync(0xffffffffu, fs, o);
        if (lane == 0) wfs[wid] = fs;
        __syncthreads();
        if (t == 0) {
            float tot = 0.0f;
#pragma unroll
            for (int i2 = 0; i2 < 32; i2++) tot += wfs[i2];
            g_sumd = tot;
        }
    }
}

__global__ void k_pi() {
    int i = blockIdx.x * blockDim.x + threadIdx.x;
    if (i >= NN) return;
    float di = g_d[i];
    float p = di / g_sumd;
    g_pi[i] = p;
    g_invd[i] = 1.0f / di;
    atomicAdd(&g_sumpi, (double)p);
    int idx = atomicAdd(&g_rowpos[i], 1);
    g_cols[idx] = i;
    g_cvals[idx] = 1.0f;
}

// fused: CSR scatter + query-id scatter
__global__ void k_scatter(const int* __restrict__ AE, const int* __restrict__ Q,
                          int E, int EB) {
    if ((int)blockIdx.x < EB) {
        int e = blockIdx.x * 256 + threadIdx.x;
        if (e >= E) return;
        int u = idx_at(AE, 2 * e), v = idx_at(AE, 2 * e + 1);
        float a = g_aval[e];
        int i1 = atomicAdd(&g_rowpos[u], 1); g_cols[i1] = v; g_cvals[i1] = a;
        int i2 = atomicAdd(&g_rowpos[v], 1); g_cols[i2] = u; g_cvals[i2] = a;
    } else {
        int q = (blockIdx.x - EB) * 256 + threadIdx.x;
        if (q >= EQN) return;
        int i = idx_at(Q, 2 * q);
        int idx = atomicAdd(&g_qpos[i], 1);
        g_qid[idx] = q;
    }
}

__global__ void __launch_bounds__(256) k_row(const int* __restrict__ Q) {
    __shared__ float acc[NN];
    __shared__ float s1[8], s2[8];
    int i = blockIdx.x;
    int t = threadIdx.x;
    for (int c = t; c < NN; c += 256) acc[c] = 0.0f;
    __syncthreads();

    int rs = g_rowstart[i], re = g_rowstart[i + 1];
    float idi = g_invd[i];
    int warp = t >> 5, lane = t & 31;
    for (int jj = rs + warp; jj < re; jj += 8) {
        int j = g_cols[jj];
        float sscale = g_cvals[jj] * idi * g_invd[j];
        int js = g_rowstart[j], je = g_rowstart[j + 1];
        for (int kk = js + lane; kk < je; kk += 32)
            atomicAdd(&acc[g_cols[kk]], sscale * g_cvals[kk]);
    }
    __syncthreads();

    float srow = 0.0f, ssq = 0.0f;
    for (int c = t; c < NN; c += 256) {
        float a = acc[c];
        srow += a;
        float dd = a - g_pi[c];
        ssq = fmaf(dd, dd, ssq);
    }
#pragma unroll
    for (int o = 16; o; o >>= 1) {
        srow += __shfl_down_sync(0xffffffffu, srow, o);
        ssq  += __shfl_down_sync(0xffffffffu, ssq, o);
    }
    if (lane == 0) { s1[warp] = srow; s2[warp] = ssq; }
    __syncthreads();
    if (t == 0) {
        float S1 = 0.0f, S2 = 0.0f;
#pragma unroll
        for (int w2 = 0; w2 < 8; w2++) { S1 += s1[w2]; S2 += s2[w2]; }
        float pii = g_pi[i];
        atomicAdd(&g_G1, (double)pii * (double)S1);
        atomicAdd(&g_G2, (double)pii * (double)pii * (double)S2);
    }
    int qs = g_qstart[i], qe = g_qstart[i + 1];
    for (int q = qs + t; q < qe; q += 256) {
        int qq = g_qid[q];
        int j1 = idx_at(Q, 2 * qq + 1);
        g_pval[qq] = acc[j1];
    }
}

__global__ void k_final(const int* __restrict__ Q, float* __restrict__ out) {
    int q = blockIdx.x * blockDim.x + threadIdx.x;
    if (q >= EQN) return;
    double n2 = (double)NN * (double)NN;
    double sp = g_sumpi;
    double mean = (g_G1 - sp * sp) / n2;
    double var = (g_G2 - n2 * mean * mean) / (n2 - 1.0);
    double istd = rsqrt(var);
    int i = idx_at(Q, 2 * q), j = idx_at(Q, 2 * q + 1);
    double r = (double)g_pi[i] * ((double)g_pval[q] - (double)g_pi[j]);
    out[q] = (float)((r - mean) * istd);
}

// ---------------- launch ----------------
extern "C" void kernel_launch(void* const* d_in, const int* in_sizes, int n_in,
                              void* d_out, int out_size) {
    const float* X  = (const float*)d_in[0];
    const float* A  = (const float*)d_in[1];
    const float* S  = (const float*)d_in[2];
    const int*   AE = (const int*)d_in[4];
    const int*   Q  = (const int*)d_in[5];
    const float* W1 = (const float*)d_in[6];
    const float* b1 = (const float*)d_in[7];
    const float* W2 = (const float*)d_in[8];
    const float* b2 = (const float*)d_in[9];
    const float* W3 = (const float*)d_in[10];
    const float* b3 = (const float*)d_in[11];
    float* out = (float*)d_out;
    int E = in_sizes[4] / 2;
    int EB = (E + 255) / 256;
    int QB = (EQN + 255) / 256;

    k_init<<<(NN + 255) / 256, 256>>>(AE);
    k_prep<<<(HH * HH + 255) / 256, 256>>>(W1, W2, W3);
    k_xw<<<NN / 32, 128>>>(X, W1);
    k_mlp<<<(E + 63) / 64, 128>>>(X, AE, b1, b2, b3, E);
    k_edge_qcnt<<<EB + QB, 256>>>(A, S, AE, Q, E, EB);
    k_scan<<<1, 1024>>>();
    k_pi<<<(NN + 255) / 256, 256>>>();
    k_scatter<<<EB + QB, 256>>>(AE, Q, E, EB);
    k_row<<<NN, 256>>>(Q);
    k_final<<<(EQN + 255) / 256, 256>>>(Q, out);
}